// round 1
// baseline (speedup 1.0000x reference)
#include <cuda_runtime.h>

#define TILE 256
#define MAX_TILES 64   // supports N up to 16384

// Per-block partial sums (deterministic two-stage reduction; no float atomics).
__device__ float g_partials[MAX_TILES * MAX_TILES];

__device__ __forceinline__ float pair_term(float d2, float rinv) {
    // term = f_switch/sqrt(r^2+1) + (1-f_switch)/r
    float term = rinv;                    // r >= r_off: fs = 0 -> 1/r
    if (d2 < 25.0f) {
        float fs;
        if (d2 <= 9.0f) {
            fs = 1.0f;                    // r <= r_on: fs = 1
        } else {
            float r  = d2 * rinv;         // r = sqrt(d2)
            float a  = (r - 3.0f) * 0.5f; // (r - r_on) / (r_off - r_on), in (0,1)
            float s1 = __expf(-1.0f / (1.0f - a)); // sigma(1 - a)
            float s2 = __expf(-1.0f / a);          // sigma(a)
            fs = s1 / (s1 + s2);
        }
        float inv_sq = rsqrtf(d2 + 1.0f); // 1/sqrt(r^2+1)
        term = fmaf(fs, inv_sq - rinv, rinv);
    }
    return term;
}

__global__ __launch_bounds__(TILE)
void elec_pair_kernel(const float* __restrict__ q,
                      const float* __restrict__ xyz,
                      int n, int nTiles) {
    const int bi = blockIdx.y;   // i-tile
    const int bj = blockIdx.x;   // j-tile
    const int bid = bi * nTiles + bj;
    const int t = threadIdx.x;

    __shared__ float4 tile[TILE];
    __shared__ float warpsum[TILE / 32];

    // Lower-triangle blocks: contribute nothing (but must write deterministically).
    if (bj < bi) {
        if (t == 0) g_partials[bid] = 0.0f;
        return;
    }

    const int j0 = bj * TILE;
    const int jg = j0 + t;
    if (jg < n) {
        tile[t] = make_float4(xyz[3 * jg], xyz[3 * jg + 1], xyz[3 * jg + 2], q[jg]);
    } else {
        tile[t] = make_float4(0.0f, 0.0f, 0.0f, 0.0f);
    }
    __syncthreads();

    const int ig = bi * TILE + t;
    float acc = 0.0f;

    if (ig < n) {
        const float xi = xyz[3 * ig];
        const float yi = xyz[3 * ig + 1];
        const float zi = xyz[3 * ig + 2];
        const float qi = q[ig];
        const int jcount = min(TILE, n - j0);

        if (bi == bj) {
            // Diagonal tile: only j > i, i.e. k > t. Distinct points => d2 > 0.
            for (int k = t + 1; k < jcount; k++) {
                float4 p = tile[k];
                float dx = xi - p.x, dy = yi - p.y, dz = zi - p.z;
                float d2 = fmaf(dx, dx, fmaf(dy, dy, dz * dz));
                float rinv = rsqrtf(d2);
                acc = fmaf(qi * p.w, pair_term(d2, rinv), acc);
            }
        } else {
            // Strict upper off-diagonal tile: all pairs valid.
            #pragma unroll 4
            for (int k = 0; k < jcount; k++) {
                float4 p = tile[k];
                float dx = xi - p.x, dy = yi - p.y, dz = zi - p.z;
                float d2 = fmaf(dx, dx, fmaf(dy, dy, dz * dz));
                float rinv = rsqrtf(d2);
                acc = fmaf(qi * p.w, pair_term(d2, rinv), acc);
            }
        }
    }

    // Block reduction: warp shfl then cross-warp via smem.
    #pragma unroll
    for (int off = 16; off > 0; off >>= 1)
        acc += __shfl_down_sync(0xFFFFFFFFu, acc, off);
    if ((t & 31) == 0) warpsum[t >> 5] = acc;
    __syncthreads();
    if (t == 0) {
        float s = 0.0f;
        #pragma unroll
        for (int w = 0; w < TILE / 32; w++) s += warpsum[w];
        g_partials[bid] = s;
    }
}

__global__ __launch_bounds__(1024)
void elec_reduce_kernel(float* __restrict__ out, int total) {
    __shared__ float s[1024];
    float acc = 0.0f;
    for (int i = threadIdx.x; i < total; i += 1024)
        acc += g_partials[i];
    s[threadIdx.x] = acc;
    __syncthreads();
    #pragma unroll
    for (int stride = 512; stride > 0; stride >>= 1) {
        if (threadIdx.x < stride) s[threadIdx.x] += s[threadIdx.x + stride];
        __syncthreads();
    }
    if (threadIdx.x == 0)
        out[0] = s[0] * 332.0637f;  // KE_KCAL applied once at the end
}

extern "C" void kernel_launch(void* const* d_in, const int* in_sizes, int n_in,
                              void* d_out, int out_size) {
    const float* q   = (const float*)d_in[0];
    const float* xyz = (const float*)d_in[1];
    float* out = (float*)d_out;

    int n = in_sizes[0];
    int nTiles = (n + TILE - 1) / TILE;
    if (nTiles > MAX_TILES) nTiles = MAX_TILES;  // problem is fixed at N=8192 (32 tiles)

    dim3 grid(nTiles, nTiles);
    elec_pair_kernel<<<grid, TILE>>>(q, xyz, n, nTiles);
    elec_reduce_kernel<<<1, 1024>>>(out, nTiles * nTiles);
}

// round 3
// speedup vs baseline: 1.6941x; 1.6941x over previous
#include <cuda_runtime.h>

#define TILE 256
#define MAX_BLOCKS 4096   // >= T*(T+1)/2 for N<=16384 (T=64 -> 2080)

__device__ float g_partials[MAX_BLOCKS];
__device__ int   g_counter = 0;   // self-resetting arrival counter

__device__ __forceinline__ float pair_term(float d2, float rinv) {
    // term = fs/sqrt(r^2+1) + (1-fs)/r ;  fs=0 for r>=5
    float term = rinv;
    if (d2 < 25.0f) {
        float r = d2 * rinv;                       // r = sqrt(d2)
        float a = (r - 3.0f) * 0.5f;               // (r-r_on)/(r_off-r_on)
        a = fminf(fmaxf(a, 1e-7f), 1.0f);          // clamp: a<=0 -> fs=1, a~1 -> fs->0
        float s1 = __expf(__fdividef(-1.0f, 1.0f - a)); // sigma(1-a)
        float s2 = __expf(__fdividef(-1.0f, a));        // sigma(a)
        float fs = __fdividef(s1, s1 + s2);
        float inv_sq = rsqrtf(d2 + 1.0f);
        term = fmaf(fs, inv_sq - rinv, rinv);
    }
    return term;
}

__global__ __launch_bounds__(TILE)
void elec_pair_kernel(const float* __restrict__ q,
                      const float* __restrict__ xyz,
                      float* __restrict__ out,
                      int n, int nTiles, int nBlocks) {
    // Map linear block id -> upper-triangle tile (bi, bj), bj >= bi.
    const int bid = blockIdx.x;
    int bi;
    {
        float fT = (float)nTiles;
        float disc = (fT + 0.5f) * (fT + 0.5f) - 2.0f * (float)bid;
        bi = (int)(fT + 0.5f - sqrtf(fmaxf(disc, 0.0f)));
        if (bi < 0) bi = 0;
        // correct float rounding: start(i) = i*nTiles - i*(i-1)/2
        while (bi > 0 && bid < bi * nTiles - (bi * (bi - 1)) / 2) bi--;
        while (bid >= (bi + 1) * nTiles - ((bi + 1) * bi) / 2) bi++;
    }
    const int bj = bi + (bid - (bi * nTiles - (bi * (bi - 1)) / 2));

    const int t = threadIdx.x;
    __shared__ float4 tile[TILE];
    __shared__ float warpsum[TILE / 32];
    __shared__ int lastFlag;

    const int j0 = bj * TILE;
    const int jg = j0 + t;
    if (jg < n) {
        tile[t] = make_float4(xyz[3 * jg], xyz[3 * jg + 1], xyz[3 * jg + 2], q[jg]);
    } else {
        tile[t] = make_float4(1.0e9f, 1.0e9f, 1.0e9f, 0.0f); // q=0 -> no contribution
    }
    __syncthreads();

    const int ig = bi * TILE + t;
    float acc = 0.0f;

    if (ig < n) {
        const float xi = xyz[3 * ig];
        const float yi = xyz[3 * ig + 1];
        const float zi = xyz[3 * ig + 2];
        const float qi = q[ig];
        const int jcount = min(TILE, n - j0);

        if (bi == bj) {
            for (int k = t + 1; k < jcount; k++) {
                float4 p = tile[k];
                float dx = xi - p.x, dy = yi - p.y, dz = zi - p.z;
                float d2 = fmaf(dx, dx, fmaf(dy, dy, dz * dz));
                float rinv = rsqrtf(d2);
                acc = fmaf(qi * p.w, pair_term(d2, rinv), acc);
            }
        } else {
            #pragma unroll 4
            for (int k = 0; k < jcount; k++) {
                float4 p = tile[k];
                float dx = xi - p.x, dy = yi - p.y, dz = zi - p.z;
                float d2 = fmaf(dx, dx, fmaf(dy, dy, dz * dz));
                float rinv = rsqrtf(d2);
                acc = fmaf(qi * p.w, pair_term(d2, rinv), acc);
            }
        }
    }

    // Block reduction
    #pragma unroll
    for (int off = 16; off > 0; off >>= 1)
        acc += __shfl_down_sync(0xFFFFFFFFu, acc, off);
    if ((t & 31) == 0) warpsum[t >> 5] = acc;
    __syncthreads();

    if (t == 0) {
        float s = 0.0f;
        #pragma unroll
        for (int w = 0; w < TILE / 32; w++) s += warpsum[w];
        g_partials[bid] = s;
        __threadfence();
        int ticket = atomicAdd(&g_counter, 1);
        lastFlag = (ticket == nBlocks - 1) ? 1 : 0;
    }
    __syncthreads();

    // Last block to finish performs the final deterministic reduction.
    if (lastFlag) {
        float a2 = 0.0f;
        for (int i = t; i < nBlocks; i += TILE)
            a2 += g_partials[i];
        #pragma unroll
        for (int off = 16; off > 0; off >>= 1)
            a2 += __shfl_down_sync(0xFFFFFFFFu, a2, off);
        if ((t & 31) == 0) warpsum[t >> 5] = a2;
        __syncthreads();
        if (t == 0) {
            float s = 0.0f;
            #pragma unroll
            for (int w = 0; w < TILE / 32; w++) s += warpsum[w];
            out[0] = s * 332.0637f;   // KE_KCAL applied once
            g_counter = 0;            // reset for next graph replay
        }
    }
}

extern "C" void kernel_launch(void* const* d_in, const int* in_sizes, int n_in,
                              void* d_out, int out_size) {
    const float* q   = (const float*)d_in[0];
    const float* xyz = (const float*)d_in[1];
    float* out = (float*)d_out;

    int n = in_sizes[0];
    int nTiles = (n + TILE - 1) / TILE;
    int nBlocks = nTiles * (nTiles + 1) / 2;
    if (nBlocks > MAX_BLOCKS) nBlocks = MAX_BLOCKS;

    elec_pair_kernel<<<nBlocks, TILE>>>(q, xyz, out, n, nTiles, nBlocks);
}